// round 12
// baseline (speedup 1.0000x reference)
#include <cuda_runtime.h>
#include <math.h>

#define BATCH 4096
#define NCELL 81
#define DIM 128
#define ROWS (BATCH*NCELL)   /* 331776 */

typedef unsigned long long u64;

/* ------------- static device scratch (no cudaMalloc allowed) ------------- */
__device__ float  g_x  [(size_t)ROWS*DIM];   /* stem+emb; later LN out         */
__device__ float  g_c  [(size_t)ROWS*DIM];   /* ctx; later mlp out             */
__device__ float  g_qkv[(size_t)ROWS*384];
__device__ int    g_dig[ROWS];
__device__ float  g_M  [10*9*128];           /* collapsed conv1+conv2 table    */
__device__ float4 g_w3v[9*32*128];           /* c3 weights [k][ic4][oc] f4     */
__device__ float4 g_wv [24576];              /* in(12288) out(4096) l1 l2      */

/* ---------------- packed f32x2 helpers (FFMA2) ---------------------------- */
__device__ __forceinline__ void fma2(u64& acc, u64 a, u64 b) {
  asm("fma.rn.f32x2 %0, %1, %2, %0;" : "+l"(acc) : "l"(a), "l"(b));
}
__device__ __forceinline__ u64 pack2(float lo, float hi) {
  u64 r; asm("mov.b64 %0, {%1, %2};" : "=l"(r) : "f"(lo), "f"(hi)); return r;
}
__device__ __forceinline__ float red2(u64 a) {
  float lo, hi; asm("mov.b64 {%0, %1}, %2;" : "=f"(lo), "=f"(hi) : "l"(a));
  return lo + hi;
}
__device__ __forceinline__ void unp2(u64 a, float& lo, float& hi) {
  asm("mov.b64 {%0, %1}, %2;" : "=f"(lo), "=f"(hi) : "l"(a));
}

/* ---------------- threefry2x32 (bit-exact vs jax.random) ----------------- */
__host__ __device__ __forceinline__ void tf2x32(unsigned k0, unsigned k1,
                                                unsigned x0, unsigned x1,
                                                unsigned* o0, unsigned* o1) {
  unsigned ks2 = k0 ^ k1 ^ 0x1BD11BDAu;
  x0 += k0; x1 += k1;
#define TFR(r) { x0 += x1; x1 = (x1 << (r)) | (x1 >> (32-(r))); x1 ^= x0; }
  TFR(13) TFR(15) TFR(26) TFR(6)   x0 += k1;  x1 += ks2 + 1u;
  TFR(17) TFR(29) TFR(16) TFR(24)  x0 += ks2; x1 += k0  + 2u;
  TFR(13) TFR(15) TFR(26) TFR(6)   x0 += k0;  x1 += k1  + 3u;
  TFR(17) TFR(29) TFR(16) TFR(24)  x0 += k1;  x1 += ks2 + 4u;
  TFR(13) TFR(15) TFR(26) TFR(6)   x0 += ks2; x1 += k0  + 5u;
#undef TFR
  *o0 = x0; *o1 = x1;
}

/* partitionable-threefry gumbel: bits[idx] = o0^o1 of tf(key, (0, idx)) */
__device__ __forceinline__ float gumbel_at(unsigned kk0, unsigned kk1, unsigned idx) {
  unsigned o0, o1;
  tf2x32(kk0, kk1, 0u, idx, &o0, &o1);
  unsigned bits = o0 ^ o1;
  float f = __uint_as_float((bits >> 9) | 0x3f800000u) - 1.0f;    /* [0,1) */
  const float tiny = 1.1754943508222875e-38f;
  float u = fmaxf(tiny, f + tiny);
  return -logf(-logf(u));
}

__device__ __forceinline__ float silu_f(float a) { return a / (1.0f + expf(-a)); }

/* ------------------------------ prep kernels ----------------------------- */
__global__ void k_digits(const float* __restrict__ s) {
  int idx = blockIdx.x * 256 + threadIdx.x;
  if (idx >= ROWS) return;
  int b = idx / 81, n = idx - b * 81;
  const float* sp = s + (size_t)b * 810 + n;     /* [B,10,9,9], ch stride 81 */
  int d = 0;
  #pragma unroll
  for (int dd = 0; dd < 10; dd++) if (sp[dd * 81] > 0.5f) d = dd;
  g_dig[idx] = d;
}

/* M[d][k][o] = sum_i c2_w[o,i,k]*(c1_w[i,d]+c1_b[i]) */
__global__ void k_M(const float* __restrict__ c1w, const float* __restrict__ c1b,
                    const float* __restrict__ c2w) {
  int t = blockIdx.x * 128 + threadIdx.x;
  if (t >= 11520) return;
  int o = t & 127, dk = t >> 7, d = dk / 9, k = dk - 9 * d;
  float s = 0.f;
  for (int i = 0; i < 64; i++)
    s += c2w[(o * 64 + i) * 9 + k] * (c1w[i * 10 + d] + c1b[i]);
  g_M[(d * 9 + k) * 128 + o] = s;
}

/* transpose weights: w3v for conv3, wv for the 4 GEMMs */
__global__ void k_wtrans(const float* __restrict__ c3,  const float* __restrict__ inw,
                         const float* __restrict__ outw, const float* __restrict__ l1w,
                         const float* __restrict__ l2w) {
  int t = blockIdx.x * 256 + threadIdx.x;
  if (t < 36864) {                        /* w3v[(k*32+j)*128+o] = c3[o][4j..][k] */
    int o = t & 127, kj = t >> 7, k = kj >> 5, j = kj & 31;
    const float* p = c3 + ((size_t)o * 128 + 4 * j) * 9 + k;
    g_w3v[t] = make_float4(p[0], p[9], p[18], p[27]);
  } else {
    int u = t - 36864;                    /* wv[g*KOUT + j] = W[j][4g..4g+3]      */
    const float* W; int KOUT, base;
    if (u < 12288) { W = inw; KOUT = 384; base = 0; }
    else {
      int v = u - 12288; int m = v / 4096; v -= m * 4096;
      W = (m == 0) ? outw : (m == 1) ? l1w : l2w;
      KOUT = 128; base = 12288 + m * 4096; u = v;
    }
    int g = u / KOUT, j = u - g * KOUT;
    g_wv[base + u] = ((const float4*)W)[j * 32 + g];
  }
}

/* ------------------- conv3 (y2 fused in), FFMA2 --------------------------- */
template<int BASE>
__device__ __forceinline__ void conv3_cells(const u64* __restrict__ y2p2,
                                            int oc, u64* acc) {
  const u64* wvb = (const u64*)g_w3v;
  #pragma unroll 1
  for (int k = 0; k < 9; k++) {
    int koff32 = ((k / 3) * 11 + (k % 3)) * 32;
    #pragma unroll 1
    for (int j = 0; j < 32; j++) {
      const u64* wp = wvb + 2 * ((size_t)(k * 32 + j) * 128 + oc);
      u64 w0 = wp[0], w1 = wp[1];
      const u64* yb = y2p2 + 2 * (koff32 + j);
      #pragma unroll
      for (int c = 0; c < 27; c++) {
        const int cell = BASE + c;
        const int cb = (cell / 9) * 11 + (cell % 9);   /* compile-time */
        u64 y0 = yb[cb * 64], y1 = yb[cb * 64 + 1];
        fma2(acc[c], w0, y0);
        fma2(acc[c], w1, y1);
      }
    }
  }
}

__global__ void __launch_bounds__(384)
k_conv3(const float* __restrict__ c2b, const float* __restrict__ c3b,
        const float* __restrict__ emb) {
  extern __shared__ float sm[];
  float* Ms  = sm;                               /* 11520                     */
  float* y2p = sm + 11520;                       /* [11][11][128] halo-padded */
  __shared__ int dg[81];
  int b = blockIdx.x, t = threadIdx.x;
  for (int i = t; i < 11520; i += 384) Ms[i] = g_M[i];
  for (int i = t; i < 121 * 128; i += 384) y2p[i] = 0.f;
  if (t < 81) dg[t] = g_dig[b * 81 + t];
  __syncthreads();
  /* y2 = silu(conv2(conv1(s))) straight into the padded smem tile */
  for (int i = t; i < 81 * 128; i += 384) {
    int cell = i >> 7, ch = i & 127;
    int r = cell / 9, c = cell - 9 * r;
    float a = c2b[ch];
    #pragma unroll
    for (int k = 0; k < 9; k++) {
      int rr = r + k / 3 - 1, cc = c + k % 3 - 1;
      if (rr >= 0 && rr < 9 && cc >= 0 && cc < 9)
        a += Ms[(dg[rr * 9 + cc] * 9 + k) * 128 + ch];
    }
    y2p[((r + 1) * 11 + (c + 1)) * 128 + ch] = silu_f(a);
  }
  __syncthreads();
  int oc = t & 127, grp = t >> 7;                /* 0..2, 27 cells each */
  u64 acc[27];
  #pragma unroll
  for (int i = 0; i < 27; i++) acc[i] = 0ull;
  const u64* y2p2 = (const u64*)y2p;
  if (grp == 0)      conv3_cells<0 >(y2p2, oc, acc);
  else if (grp == 1) conv3_cells<27>(y2p2, oc, acc);
  else               conv3_cells<54>(y2p2, oc, acc);
  float bias = c3b[oc];
  int base = grp * 27;
  for (int c = 0; c < 27; c++) {
    int cell = base + c;
    float a = red2(acc[c]) + bias;
    g_x[((size_t)b * 81 + cell) * 128 + oc] = silu_f(a) + emb[cell * 128 + oc];
  }
}

/* ------------------------- qkv GEMM (FFMA2) ------------------------------- */
__global__ void __launch_bounds__(256)
k_qkv(const float* __restrict__ in, const float4* __restrict__ wv,
      const float* __restrict__ bias, float* __restrict__ out) {
  __shared__ float4 xs[32 * 32];
  int t = threadIdx.x;
  size_t row0 = (size_t)blockIdx.x * 32;
  for (int i = t; i < 1024; i += 256) {
    int r = i >> 5, g = i & 31;
    xs[i] = ((const float4*)(in + (row0 + r) * 128))[g];
  }
  __syncthreads();
  const u64* xs2 = (const u64*)xs;
  const u64* wv2 = (const u64*)wv;
  int col = t & 127, rb = (t >> 7) * 16;
  for (int p = 0; p < 3; p++) {
    int cc = p * 128 + col;
    u64 acc[16];
    #pragma unroll
    for (int r = 0; r < 16; r++) acc[r] = 0ull;
    #pragma unroll 1
    for (int g = 0; g < 32; g++) {
      u64 w0 = wv2[2 * (g * 384 + cc)], w1 = wv2[2 * (g * 384 + cc) + 1];
      #pragma unroll
      for (int r = 0; r < 16; r++) {
        u64 x0 = xs2[2 * ((rb + r) * 32 + g)], x1 = xs2[2 * ((rb + r) * 32 + g) + 1];
        fma2(acc[r], w0, x0);
        fma2(acc[r], w1, x1);
      }
    }
    float bb = bias[cc];
    for (int r = 0; r < 16; r++)
      out[(row0 + rb + r) * 384 + cc] = red2(acc[r]) + bb;
  }
}

/* --------------- out-projection GEMM + fused LayerNorm -------------------- */
__global__ void __launch_bounds__(256)
k_out_ln(const float* __restrict__ in, const float4* __restrict__ wv,
         const float* __restrict__ bias, const float* __restrict__ lng,
         const float* __restrict__ lnb, float* __restrict__ out) {
  __shared__ float4 xs[32 * 32];
  __shared__ float red[32][4];
  __shared__ float red2b[32][4];
  int t = threadIdx.x;
  size_t row0 = (size_t)blockIdx.x * 32;
  for (int i = t; i < 1024; i += 256) {
    int r = i >> 5, g = i & 31;
    xs[i] = ((const float4*)(in + (row0 + r) * 128))[g];
  }
  __syncthreads();
  const u64* xs2 = (const u64*)xs;
  const u64* wv2 = (const u64*)wv;
  int col = t & 127, rb = (t >> 7) * 16;
  u64 acc[16];
  #pragma unroll
  for (int r = 0; r < 16; r++) acc[r] = 0ull;
  #pragma unroll 1
  for (int g = 0; g < 32; g++) {
    u64 w0 = wv2[2 * (g * 128 + col)], w1 = wv2[2 * (g * 128 + col) + 1];
    #pragma unroll
    for (int r = 0; r < 16; r++) {
      u64 x0 = xs2[2 * ((rb + r) * 32 + g)], x1 = xs2[2 * ((rb + r) * 32 + g) + 1];
      fma2(acc[r], w0, x0);
      fma2(acc[r], w1, x1);
    }
  }
  float bb = bias[col];
  float a[16];
  #pragma unroll
  for (int r = 0; r < 16; r++) a[r] = red2(acc[r]) + bb;
  /* LayerNorm across cols (128 threads of this half) */
  int lane = t & 31, w4 = (t >> 5) & 3;
  #pragma unroll
  for (int r = 0; r < 16; r++) {
    float v = a[r];
    for (int o = 16; o; o >>= 1) v += __shfl_xor_sync(~0u, v, o);
    if (lane == 0) red[rb + r][w4] = v;
  }
  __syncthreads();
  float mu[16];
  #pragma unroll
  for (int r = 0; r < 16; r++)
    mu[r] = (red[rb + r][0] + red[rb + r][1] + red[rb + r][2] + red[rb + r][3]) * 0.0078125f;
  #pragma unroll
  for (int r = 0; r < 16; r++) {
    float d = a[r] - mu[r];
    float v = d * d;
    for (int o = 16; o; o >>= 1) v += __shfl_xor_sync(~0u, v, o);
    if (lane == 0) red2b[rb + r][w4] = v;
  }
  __syncthreads();
  float gg = lng[col], lb = lnb[col];
  for (int r = 0; r < 16; r++) {
    float var = (red2b[rb + r][0] + red2b[rb + r][1] + red2b[rb + r][2] + red2b[rb + r][3]) * 0.0078125f;
    float sd = __fsqrt_rn(var + 1e-5f);
    out[(row0 + rb + r) * 128 + col] = __fdiv_rn(a[r] - mu[r], sd) * gg + lb;
  }
}

/* --------------------- fused MLP: silu(l1) -> silu(l2) -------------------- */
__global__ void __launch_bounds__(256)
k_mlp(const float* __restrict__ in, const float4* __restrict__ w1v,
      const float* __restrict__ b1, const float4* __restrict__ w2v,
      const float* __restrict__ b2, float* __restrict__ out) {
  __shared__ float4 xs[32 * 32];
  __shared__ float4 hs[32 * 32];
  int t = threadIdx.x;
  size_t row0 = (size_t)blockIdx.x * 32;
  for (int i = t; i < 1024; i += 256) {
    int r = i >> 5, g = i & 31;
    xs[i] = ((const float4*)(in + (row0 + r) * 128))[g];
  }
  __syncthreads();
  int col = t & 127, rb = (t >> 7) * 16;
  {
    const u64* xs2 = (const u64*)xs;
    const u64* wv2 = (const u64*)w1v;
    u64 acc[16];
    #pragma unroll
    for (int r = 0; r < 16; r++) acc[r] = 0ull;
    #pragma unroll 1
    for (int g = 0; g < 32; g++) {
      u64 w0 = wv2[2 * (g * 128 + col)], w1 = wv2[2 * (g * 128 + col) + 1];
      #pragma unroll
      for (int r = 0; r < 16; r++) {
        u64 x0 = xs2[2 * ((rb + r) * 32 + g)], x1 = xs2[2 * ((rb + r) * 32 + g) + 1];
        fma2(acc[r], w0, x0);
        fma2(acc[r], w1, x1);
      }
    }
    float bb = b1[col];
    float* hf = (float*)hs;
    for (int r = 0; r < 16; r++)
      hf[(rb + r) * 128 + col] = silu_f(red2(acc[r]) + bb);
  }
  __syncthreads();
  {
    const u64* hs2 = (const u64*)hs;
    const u64* wv2 = (const u64*)w2v;
    u64 acc[16];
    #pragma unroll
    for (int r = 0; r < 16; r++) acc[r] = 0ull;
    #pragma unroll 1
    for (int g = 0; g < 32; g++) {
      u64 w0 = wv2[2 * (g * 128 + col)], w1 = wv2[2 * (g * 128 + col) + 1];
      #pragma unroll
      for (int r = 0; r < 16; r++) {
        u64 x0 = hs2[2 * ((rb + r) * 32 + g)], x1 = hs2[2 * ((rb + r) * 32 + g) + 1];
        fma2(acc[r], w0, x0);
        fma2(acc[r], w1, x1);
      }
    }
    float bb = b2[col];
    for (int r = 0; r < 16; r++)
      out[(row0 + rb + r) * 128 + col] = silu_f(red2(acc[r]) + bb);
  }
}

/* ----------------------------- attention ---------------------------------- */
__global__ void __launch_bounds__(384)
k_attn(float* __restrict__ asc_out) {
  extern __shared__ float sm[];
  float* ks    = sm;                 /* 81*128 */
  float* vs    = ks + 81 * 128;      /* 81*128 */
  float* probs = vs + 81 * 128;      /* 4*81*81; q staged here (stride 132)  */
  int b = blockIdx.x, t = threadIdx.x;
  size_t base = (size_t)b * 81;
  for (int i = t; i < 81 * 128; i += 384) {
    int r = i >> 7, d = i & 127;
    const float* qk = g_qkv + (base + r) * 384;
    ks[i] = qk[128 + d];
    vs[i] = qk[256 + d];
    probs[r * 132 + d] = qk[d];
  }
  __syncthreads();
  int h = t / 81, i = t - h * 81;
  bool act = (t < 324);
  u64 q2[16];
  if (act) {
    const u64* qrow = (const u64*)(probs + i * 132 + h * 32);
    #pragma unroll
    for (int m = 0; m < 16; m++) q2[m] = qrow[m];
  }
  __syncthreads();                   /* q in regs; probs area may be reused */
  if (act) {
    int ri = i / 9, ci = i - 9 * ri, bi = (ri / 3) * 3 + ci / 3;
    float* pr = probs + (h * 81 + i) * 81;
    const u64* ks2 = (const u64*)ks;
    float mx = -1e30f;
    for (int j = 0; j < 81; j++) {
      u64 s2 = 0ull;
      const u64* kp = ks2 + 2 * (j * 32 + h * 8);
      #pragma unroll
      for (int m = 0; m < 16; m++) fma2(s2, q2[m], kp[m]);
      float s = __fdiv_rn(red2(s2), 5.656854249492381f);
      int rj = j / 9, cj = j - 9 * rj;
      float m;
      if      (h == 0) m = (rj == ri) ? 1.f : 0.f;
      else if (h == 1) m = (cj == ci) ? 1.f : 0.f;
      else if (h == 2) m = (((rj / 3) * 3 + cj / 3) == bi) ? 1.f : 0.f;
      else             m = 1.f;
      s += m;
      pr[j] = s;
      mx = fmaxf(mx, s);
    }
    float den = 0.f;
    for (int j = 0; j < 81; j++) { float e = expf(pr[j] - mx); pr[j] = e; den += e; }
    for (int j = 0; j < 81; j++) pr[j] = __fdiv_rn(pr[j], den);
  }
  __syncthreads();
  float* ao = asc_out + (size_t)b * 6561;
  for (int idx = t; idx < 6561; idx += 384) {
    float a = ((probs[idx] + probs[6561 + idx]) + probs[2 * 6561 + idx]) + probs[3 * 6561 + idx];
    ao[idx] = a * 0.25f;
  }
  if (act) {
    u64 accv[16];
    #pragma unroll
    for (int m = 0; m < 16; m++) accv[m] = 0ull;
    const float* pr = probs + (h * 81 + i) * 81;
    const u64* vs2 = (const u64*)vs;
    for (int j = 0; j < 81; j++) {
      u64 pp = pack2(pr[j], pr[j]);
      const u64* vp = vs2 + 2 * (j * 32 + h * 8);
      #pragma unroll
      for (int m = 0; m < 16; m++) fma2(accv[m], pp, vp[m]);
    }
    u64* op = (u64*)(g_c + (base + i) * 128 + h * 32);
    #pragma unroll
    for (int m = 0; m < 16; m++) op[m] = accv[m];
  }
}

/* ------------------------- heads + sampling ------------------------------- */
__global__ void k_heads(const float* __restrict__ posw, const float* __restrict__ posb,
                        const float* __restrict__ numw, const float* __restrict__ numb,
                        float* __restrict__ out,
                        unsigned k1a, unsigned k1b, unsigned k2a, unsigned k2b) {
  __shared__ float xs[81 * 132];
  __shared__ float vals[81];
  __shared__ float nv[10];
  __shared__ int sh_pos;
  int b = blockIdx.x, t = threadIdx.x;
  size_t base = (size_t)b * 81;
  for (int i = t; i < 81 * 128; i += 128) {
    int r = i >> 7, d = i & 127;
    xs[r * 132 + d] = g_c[(base + r) * 128 + d];
  }
  __syncthreads();
  if (t < 81) {
    float s = 0.f;
    for (int d = 0; d < 128; d++) s += xs[t * 132 + d] * posw[d];
    s += posb[0];
    if (g_dig[base + t] != 0) s = -1e9f;
    vals[t] = s + gumbel_at(k1a, k1b, (unsigned)(b * 81 + t));
  }
  __syncthreads();
  if (t == 0) {
    int bi = 0; float bv = vals[0];
    for (int j = 1; j < 81; j++) if (vals[j] > bv) { bv = vals[j]; bi = j; }
    sh_pos = bi;
  }
  __syncthreads();
  int pos = sh_pos;
  if (t < 10) {
    float s = 0.f;
    for (int d = 0; d < 128; d++) s += xs[pos * 132 + d] * numw[t * 128 + d];
    s += numb[t];
    nv[t] = (t == 0) ? -INFINITY
                     : s + gumbel_at(k2a, k2b, (unsigned)(b * 10 + t));
  }
  __syncthreads();
  if (t == 0) {
    int bi = 0; float bv = nv[0];
    for (int j = 1; j < 10; j++) if (nv[j] > bv) { bv = nv[j]; bi = j; }
    out[b] = (float)pos;
    out[BATCH + b] = (float)bi;
  }
}

/* ------------------------------ launcher ---------------------------------- */
extern "C" void kernel_launch(void* const* d_in, const int* in_sizes, int n_in,
                              void* d_out, int out_size) {
  const float* s    = (const float*)d_in[0];
  const float* c1w  = (const float*)d_in[1];
  const float* c1b  = (const float*)d_in[2];
  const float* c2w  = (const float*)d_in[3];
  const float* c2b  = (const float*)d_in[4];
  const float* c3w  = (const float*)d_in[5];
  const float* c3b  = (const float*)d_in[6];
  const float* emb  = (const float*)d_in[7];
  const float* inw  = (const float*)d_in[8];
  const float* inb  = (const float*)d_in[9];
  const float* outw = (const float*)d_in[10];
  const float* outb = (const float*)d_in[11];
  const float* lng  = (const float*)d_in[12];
  const float* lnb  = (const float*)d_in[13];
  const float* l1w  = (const float*)d_in[14];
  const float* l1b  = (const float*)d_in[15];
  const float* l2w  = (const float*)d_in[16];
  const float* l2b  = (const float*)d_in[17];
  const float* posw = (const float*)d_in[18];
  const float* posb = (const float*)d_in[19];
  const float* numw = (const float*)d_in[20];
  const float* numb = (const float*)d_in[21];
  float* out = (float*)d_out;

  cudaFuncSetAttribute(k_conv3, cudaFuncAttributeMaxDynamicSharedMemorySize, 108032);
  cudaFuncSetAttribute(k_attn,  cudaFuncAttributeMaxDynamicSharedMemorySize, 187920);

  /* partitionable (foldlike) split of key(42) = (0, 42):
     child key i = both outputs of threefry(key, (0, i)) */
  unsigned k1a, k1b, k2a, k2b;
  tf2x32(0u, 42u, 0u, 0u, &k1a, &k1b);
  tf2x32(0u, 42u, 0u, 1u, &k2a, &k2b);

  float *px, *pc, *pqkv; float4* pwv;
  cudaGetSymbolAddress((void**)&px,   g_x);
  cudaGetSymbolAddress((void**)&pc,   g_c);
  cudaGetSymbolAddress((void**)&pqkv, g_qkv);
  cudaGetSymbolAddress((void**)&pwv,  g_wv);

  k_digits<<<ROWS / 256, 256>>>(s);
  k_M<<<90, 128>>>(c1w, c1b, c2w);
  k_wtrans<<<240, 256>>>(c3w, inw, outw, l1w, l2w);
  k_conv3<<<BATCH, 384, 108032>>>(c2b, c3b, emb);
  k_qkv<<<ROWS / 32, 256>>>(px, pwv, inb, pqkv);
  k_attn<<<BATCH, 384, 187920>>>(out + 2 * BATCH);
  k_out_ln<<<ROWS / 32, 256>>>(pc, pwv + 12288, outb, lng, lnb, px);
  k_mlp<<<ROWS / 32, 256>>>(px, pwv + 16384, l1b, pwv + 20480, l2b, pc);
  k_heads<<<BATCH, 128>>>(posw, posb, numw, numb, out, k1a, k1b, k2a, k2b);
}

// round 14
// speedup vs baseline: 1.1326x; 1.1326x over previous
#include <cuda_runtime.h>
#include <math.h>

#define BATCH 4096
#define NCELL 81
#define DIM 128
#define ROWS (BATCH*NCELL)   /* 331776 */

/* ------------- static device scratch (no cudaMalloc allowed) ------------- */
__device__ float  g_x  [(size_t)ROWS*DIM];   /* stem+emb; later LN out         */
__device__ float  g_c  [(size_t)ROWS*DIM];   /* ctx; later mlp out             */
__device__ float  g_qkv[(size_t)ROWS*384];
__device__ int    g_dig[ROWS];
__device__ float  g_M  [10*9*128];           /* collapsed conv1+conv2 table    */
__device__ float4 g_w3v[9*32*128];           /* c3 weights [k][ic4][oc] f4     */
__device__ float4 g_wv [24576];              /* in(12288) out(4096) l1 l2      */

/* ---------------- threefry2x32 (bit-exact vs jax.random) ----------------- */
__host__ __device__ __forceinline__ void tf2x32(unsigned k0, unsigned k1,
                                                unsigned x0, unsigned x1,
                                                unsigned* o0, unsigned* o1) {
  unsigned ks2 = k0 ^ k1 ^ 0x1BD11BDAu;
  x0 += k0; x1 += k1;
#define TFR(r) { x0 += x1; x1 = (x1 << (r)) | (x1 >> (32-(r))); x1 ^= x0; }
  TFR(13) TFR(15) TFR(26) TFR(6)   x0 += k1;  x1 += ks2 + 1u;
  TFR(17) TFR(29) TFR(16) TFR(24)  x0 += ks2; x1 += k0  + 2u;
  TFR(13) TFR(15) TFR(26) TFR(6)   x0 += k0;  x1 += k1  + 3u;
  TFR(17) TFR(29) TFR(16) TFR(24)  x0 += k1;  x1 += ks2 + 4u;
  TFR(13) TFR(15) TFR(26) TFR(6)   x0 += ks2; x1 += k0  + 5u;
#undef TFR
  *o0 = x0; *o1 = x1;
}

/* partitionable-threefry gumbel: bits[idx] = o0^o1 of tf(key, (0, idx)) */
__device__ __forceinline__ float gumbel_at(unsigned kk0, unsigned kk1, unsigned idx) {
  unsigned o0, o1;
  tf2x32(kk0, kk1, 0u, idx, &o0, &o1);
  unsigned bits = o0 ^ o1;
  float f = __uint_as_float((bits >> 9) | 0x3f800000u) - 1.0f;    /* [0,1) */
  const float tiny = 1.1754943508222875e-38f;
  float u = fmaxf(tiny, f + tiny);
  return -logf(-logf(u));
}

__device__ __forceinline__ float silu_f(float a) { return a / (1.0f + expf(-a)); }

/* ------------------------------ prep kernels ----------------------------- */
__global__ void k_digits(const float* __restrict__ s) {
  int idx = blockIdx.x * 256 + threadIdx.x;
  if (idx >= ROWS) return;
  int b = idx / 81, n = idx - b * 81;
  const float* sp = s + (size_t)b * 810 + n;     /* [B,10,9,9], ch stride 81 */
  int d = 0;
  #pragma unroll
  for (int dd = 0; dd < 10; dd++) if (sp[dd * 81] > 0.5f) d = dd;
  g_dig[idx] = d;
}

/* M[d][k][o] = sum_i c2_w[o,i,k]*(c1_w[i,d]+c1_b[i]) */
__global__ void k_M(const float* __restrict__ c1w, const float* __restrict__ c1b,
                    const float* __restrict__ c2w) {
  int t = blockIdx.x * 128 + threadIdx.x;
  if (t >= 11520) return;
  int o = t & 127, dk = t >> 7, d = dk / 9, k = dk - 9 * d;
  float s = 0.f;
  for (int i = 0; i < 64; i++)
    s += c2w[(o * 64 + i) * 9 + k] * (c1w[i * 10 + d] + c1b[i]);
  g_M[(d * 9 + k) * 128 + o] = s;
}

/* transpose weights: w3v for conv3, wv for the 4 GEMMs */
__global__ void k_wtrans(const float* __restrict__ c3,  const float* __restrict__ inw,
                         const float* __restrict__ outw, const float* __restrict__ l1w,
                         const float* __restrict__ l2w) {
  int t = blockIdx.x * 256 + threadIdx.x;
  if (t < 36864) {                        /* w3v[(k*32+j)*128+o] = c3[o][4j..][k] */
    int o = t & 127, kj = t >> 7, k = kj >> 5, j = kj & 31;
    const float* p = c3 + ((size_t)o * 128 + 4 * j) * 9 + k;
    g_w3v[t] = make_float4(p[0], p[9], p[18], p[27]);
  } else {
    int u = t - 36864;                    /* wv[g*KOUT + j] = W[j][4g..4g+3]      */
    const float* W; int KOUT, base;
    if (u < 12288) { W = inw; KOUT = 384; base = 0; }
    else {
      int v = u - 12288; int m = v / 4096; v -= m * 4096;
      W = (m == 0) ? outw : (m == 1) ? l1w : l2w;
      KOUT = 128; base = 12288 + m * 4096; u = v;
    }
    int g = u / KOUT, j = u - g * KOUT;
    g_wv[base + u] = ((const float4*)W)[j * 32 + g];
  }
}

/* ---------------- conv3 with fused y2 stage (scalar float4) --------------- */
template<int BASE>
__device__ __forceinline__ void conv3_cells(const float4* __restrict__ y2p4,
                                            int oc, float* acc) {
  #pragma unroll 1
  for (int k = 0; k < 9; k++) {
    int koff32 = ((k / 3) * 11 + (k % 3)) * 32;
    const float4* wr = g_w3v + (k * 32) * 128 + oc;
    #pragma unroll 1
    for (int j = 0; j < 32; j++) {
      float4 w = wr[j * 128];
      const float4* yb = y2p4 + koff32 + j;
      #pragma unroll
      for (int c = 0; c < 41; c++) {
        const int cell = BASE + c;
        const int cb = (cell / 9) * 11 + (cell % 9);   /* compile-time */
        float4 y = yb[cb * 32];
        acc[c] += w.x * y.x; acc[c] += w.y * y.y;
        acc[c] += w.z * y.z; acc[c] += w.w * y.w;
      }
    }
  }
}

__global__ void __launch_bounds__(256)
k_conv3(const float* __restrict__ c2b, const float* __restrict__ c3b,
        const float* __restrict__ emb) {
  extern __shared__ float y2p[];                 /* [11][11][128] halo-padded */
  __shared__ int dg[81];
  int b = blockIdx.x, t = threadIdx.x;
  for (int i = t; i < 121 * 128; i += 256) y2p[i] = 0.f;
  if (t < 81) dg[t] = g_dig[b * 81 + t];
  __syncthreads();
  /* y2 = silu(conv2(conv1(s))) straight into the padded smem tile;
     M table read via L1/L2 (coalesced 128B lines, hot after first block) */
  for (int i = t; i < 81 * 128; i += 256) {
    int cell = i >> 7, ch = i & 127;
    int r = cell / 9, c = cell - 9 * r;
    float a = c2b[ch];
    #pragma unroll
    for (int k = 0; k < 9; k++) {
      int rr = r + k / 3 - 1, cc = c + k % 3 - 1;
      if (rr >= 0 && rr < 9 && cc >= 0 && cc < 9)
        a += __ldg(&g_M[(dg[rr * 9 + cc] * 9 + k) * 128 + ch]);
    }
    y2p[((r + 1) * 11 + (c + 1)) * 128 + ch] = silu_f(a);
  }
  __syncthreads();
  int oc = t & 127, grp = t >> 7;
  float acc[41];
  #pragma unroll
  for (int i = 0; i < 41; i++) acc[i] = 0.f;
  const float4* y2p4 = (const float4*)y2p;
  if (grp == 0) conv3_cells<0 >(y2p4, oc, acc);
  else          conv3_cells<40>(y2p4, oc, acc);
  float bias = c3b[oc];
  int base = grp * 40;
  for (int c = 0; c < 41; c++) {
    int cell = base + c;
    float a = acc[c] + bias;
    g_x[((size_t)b * 81 + cell) * 128 + oc] = silu_f(a) + emb[cell * 128 + oc];
  }
}

/* ------------------------- qkv GEMM (scalar float4) ----------------------- */
__global__ void __launch_bounds__(256)
k_qkv(const float* __restrict__ in, const float4* __restrict__ wv,
      const float* __restrict__ bias, float* __restrict__ out) {
  __shared__ float4 xs[32 * 32];
  int t = threadIdx.x;
  size_t row0 = (size_t)blockIdx.x * 32;
  for (int i = t; i < 1024; i += 256) {
    int r = i >> 5, g = i & 31;
    xs[i] = ((const float4*)(in + (row0 + r) * 128))[g];
  }
  __syncthreads();
  int col = t & 127, rb = (t >> 7) * 16;
  for (int p = 0; p < 3; p++) {
    int cc = p * 128 + col;
    float acc[16];
    #pragma unroll
    for (int r = 0; r < 16; r++) acc[r] = 0.f;
    #pragma unroll 1
    for (int g = 0; g < 32; g++) {
      float4 w = wv[g * 384 + cc];
      #pragma unroll
      for (int r = 0; r < 16; r++) {
        float4 x = xs[(rb + r) * 32 + g];
        acc[r] += w.x * x.x; acc[r] += w.y * x.y;
        acc[r] += w.z * x.z; acc[r] += w.w * x.w;
      }
    }
    float bb = bias[cc];
    for (int r = 0; r < 16; r++)
      out[(row0 + rb + r) * 384 + cc] = acc[r] + bb;
  }
}

/* --------------- out-projection GEMM + fused LayerNorm -------------------- */
__global__ void __launch_bounds__(256)
k_out_ln(const float* __restrict__ in, const float4* __restrict__ wv,
         const float* __restrict__ bias, const float* __restrict__ lng,
         const float* __restrict__ lnb, float* __restrict__ out) {
  __shared__ float4 xs[32 * 32];
  __shared__ float red1[32][4];
  __shared__ float red2[32][4];
  int t = threadIdx.x;
  size_t row0 = (size_t)blockIdx.x * 32;
  for (int i = t; i < 1024; i += 256) {
    int r = i >> 5, g = i & 31;
    xs[i] = ((const float4*)(in + (row0 + r) * 128))[g];
  }
  __syncthreads();
  int col = t & 127, rb = (t >> 7) * 16;
  float acc[16];
  #pragma unroll
  for (int r = 0; r < 16; r++) acc[r] = 0.f;
  #pragma unroll 1
  for (int g = 0; g < 32; g++) {
    float4 w = wv[g * 128 + col];
    #pragma unroll
    for (int r = 0; r < 16; r++) {
      float4 x = xs[(rb + r) * 32 + g];
      acc[r] += w.x * x.x; acc[r] += w.y * x.y;
      acc[r] += w.z * x.z; acc[r] += w.w * x.w;
    }
  }
  float bb = bias[col];
  float a[16];
  #pragma unroll
  for (int r = 0; r < 16; r++) a[r] = acc[r] + bb;
  /* LayerNorm across the 128 cols held by this half's 128 threads */
  int lane = t & 31, w4 = (t >> 5) & 3;
  #pragma unroll
  for (int r = 0; r < 16; r++) {
    float v = a[r];
    for (int o = 16; o; o >>= 1) v += __shfl_xor_sync(~0u, v, o);
    if (lane == 0) red1[rb + r][w4] = v;
  }
  __syncthreads();
  float mu[16];
  #pragma unroll
  for (int r = 0; r < 16; r++)
    mu[r] = (red1[rb + r][0] + red1[rb + r][1] + red1[rb + r][2] + red1[rb + r][3]) * 0.0078125f;
  #pragma unroll
  for (int r = 0; r < 16; r++) {
    float d = a[r] - mu[r];
    float v = d * d;
    for (int o = 16; o; o >>= 1) v += __shfl_xor_sync(~0u, v, o);
    if (lane == 0) red2[rb + r][w4] = v;
  }
  __syncthreads();
  float gg = lng[col], lb = lnb[col];
  for (int r = 0; r < 16; r++) {
    float var = (red2[rb + r][0] + red2[rb + r][1] + red2[rb + r][2] + red2[rb + r][3]) * 0.0078125f;
    float sd = __fsqrt_rn(var + 1e-5f);
    out[(row0 + rb + r) * 128 + col] = __fdiv_rn(a[r] - mu[r], sd) * gg + lb;
  }
}

/* --------------------- fused MLP: silu(l1) -> silu(l2) -------------------- */
__global__ void __launch_bounds__(256)
k_mlp(const float* __restrict__ in, const float4* __restrict__ w1v,
      const float* __restrict__ b1, const float4* __restrict__ w2v,
      const float* __restrict__ b2, float* __restrict__ out) {
  __shared__ float4 xs[32 * 32];
  __shared__ float4 hs[32 * 32];
  int t = threadIdx.x;
  size_t row0 = (size_t)blockIdx.x * 32;
  for (int i = t; i < 1024; i += 256) {
    int r = i >> 5, g = i & 31;
    xs[i] = ((const float4*)(in + (row0 + r) * 128))[g];
  }
  __syncthreads();
  int col = t & 127, rb = (t >> 7) * 16;
  {
    float acc[16];
    #pragma unroll
    for (int r = 0; r < 16; r++) acc[r] = 0.f;
    #pragma unroll 1
    for (int g = 0; g < 32; g++) {
      float4 w = w1v[g * 128 + col];
      #pragma unroll
      for (int r = 0; r < 16; r++) {
        float4 x = xs[(rb + r) * 32 + g];
        acc[r] += w.x * x.x; acc[r] += w.y * x.y;
        acc[r] += w.z * x.z; acc[r] += w.w * x.w;
      }
    }
    float bb = b1[col];
    float* hf = (float*)hs;
    for (int r = 0; r < 16; r++)
      hf[(rb + r) * 128 + col] = silu_f(acc[r] + bb);
  }
  __syncthreads();
  {
    float acc[16];
    #pragma unroll
    for (int r = 0; r < 16; r++) acc[r] = 0.f;
    #pragma unroll 1
    for (int g = 0; g < 32; g++) {
      float4 w = w2v[g * 128 + col];
      #pragma unroll
      for (int r = 0; r < 16; r++) {
        float4 x = hs[(rb + r) * 32 + g];
        acc[r] += w.x * x.x; acc[r] += w.y * x.y;
        acc[r] += w.z * x.z; acc[r] += w.w * x.w;
      }
    }
    float bb = b2[col];
    for (int r = 0; r < 16; r++)
      out[(row0 + rb + r) * 128 + col] = silu_f(acc[r] + bb);
  }
}

/* ----------------------------- attention ---------------------------------- */
__global__ void __launch_bounds__(384)
k_attn(float* __restrict__ asc_out) {
  extern __shared__ float sm[];
  float* ks    = sm;                 /* 81*128 */
  float* vs    = ks + 81 * 128;      /* 81*128 */
  float* probs = vs + 81 * 128;      /* 4*81*81; q staged here (stride 132)  */
  int b = blockIdx.x, t = threadIdx.x;
  size_t base = (size_t)b * 81;
  for (int i = t; i < 81 * 128; i += 384) {
    int r = i >> 7, d = i & 127;
    const float* qk = g_qkv + (base + r) * 384;
    ks[i] = qk[128 + d];
    vs[i] = qk[256 + d];
    probs[r * 132 + d] = qk[d];
  }
  __syncthreads();
  int h = t / 81, i = t - h * 81;
  bool act = (t < 324);
  float q[32];
  if (act) {
    #pragma unroll
    for (int d = 0; d < 32; d++) q[d] = probs[i * 132 + h * 32 + d];
  }
  __syncthreads();                   /* q in regs; probs area may be reused */
  if (act) {
    int ri = i / 9, ci = i - 9 * ri, bi = (ri / 3) * 3 + ci / 3;
    float* pr = probs + (h * 81 + i) * 81;
    float mx = -1e30f;
    for (int j = 0; j < 81; j++) {
      float s = 0.f;
      #pragma unroll
      for (int d = 0; d < 32; d++) s += q[d] * ks[j * 128 + h * 32 + d];
      s = __fdiv_rn(s, 5.656854249492381f);
      int rj = j / 9, cj = j - 9 * rj;
      float m;
      if      (h == 0) m = (rj == ri) ? 1.f : 0.f;
      else if (h == 1) m = (cj == ci) ? 1.f : 0.f;
      else if (h == 2) m = (((rj / 3) * 3 + cj / 3) == bi) ? 1.f : 0.f;
      else             m = 1.f;
      s += m;
      pr[j] = s;
      mx = fmaxf(mx, s);
    }
    float den = 0.f;
    for (int j = 0; j < 81; j++) { float e = expf(pr[j] - mx); pr[j] = e; den += e; }
    for (int j = 0; j < 81; j++) pr[j] = __fdiv_rn(pr[j], den);
  }
  __syncthreads();
  float* ao = asc_out + (size_t)b * 6561;
  for (int idx = t; idx < 6561; idx += 384) {
    float a = ((probs[idx] + probs[6561 + idx]) + probs[2 * 6561 + idx]) + probs[3 * 6561 + idx];
    ao[idx] = a * 0.25f;
  }
  if (act) {
    float accv[32];
    #pragma unroll
    for (int d = 0; d < 32; d++) accv[d] = 0.f;
    const float* pr = probs + (h * 81 + i) * 81;
    for (int j = 0; j < 81; j++) {
      float p = pr[j];
      #pragma unroll
      for (int d = 0; d < 32; d++) accv[d] += p * vs[j * 128 + h * 32 + d];
    }
    float* op = g_c + (base + i) * 128 + h * 32;
    #pragma unroll
    for (int d = 0; d < 32; d++) op[d] = accv[d];
  }
}

/* ------------------------- heads + sampling ------------------------------- */
__global__ void k_heads(const float* __restrict__ posw, const float* __restrict__ posb,
                        const float* __restrict__ numw, const float* __restrict__ numb,
                        float* __restrict__ out,
                        unsigned k1a, unsigned k1b, unsigned k2a, unsigned k2b) {
  __shared__ float xs[81 * 132];
  __shared__ float vals[81];
  __shared__ float nv[10];
  __shared__ int sh_pos;
  int b = blockIdx.x, t = threadIdx.x;
  size_t base = (size_t)b * 81;
  for (int i = t; i < 81 * 128; i += 128) {
    int r = i >> 7, d = i & 127;
    xs[r * 132 + d] = g_c[(base + r) * 128 + d];
  }
  __syncthreads();
  if (t < 81) {
    float s = 0.f;
    for (int d = 0; d < 128; d++) s += xs[t * 132 + d] * posw[d];
    s += posb[0];
    if (g_dig[base + t] != 0) s = -1e9f;
    vals[t] = s + gumbel_at(k1a, k1b, (unsigned)(b * 81 + t));
  }
  __syncthreads();
  if (t == 0) {
    int bi = 0; float bv = vals[0];
    for (int j = 1; j < 81; j++) if (vals[j] > bv) { bv = vals[j]; bi = j; }
    sh_pos = bi;
  }
  __syncthreads();
  int pos = sh_pos;
  if (t < 10) {
    float s = 0.f;
    for (int d = 0; d < 128; d++) s += xs[pos * 132 + d] * numw[t * 128 + d];
    s += numb[t];
    nv[t] = (t == 0) ? -INFINITY
                     : s + gumbel_at(k2a, k2b, (unsigned)(b * 10 + t));
  }
  __syncthreads();
  if (t == 0) {
    int bi = 0; float bv = nv[0];
    for (int j = 1; j < 10; j++) if (nv[j] > bv) { bv = nv[j]; bi = j; }
    out[b] = (float)pos;
    out[BATCH + b] = (float)bi;
  }
}

/* ------------------------------ launcher ---------------------------------- */
extern "C" void kernel_launch(void* const* d_in, const int* in_sizes, int n_in,
                              void* d_out, int out_size) {
  const float* s    = (const float*)d_in[0];
  const float* c1w  = (const float*)d_in[1];
  const float* c1b  = (const float*)d_in[2];
  const float* c2w  = (const float*)d_in[3];
  const float* c2b  = (const float*)d_in[4];
  const float* c3w  = (const float*)d_in[5];
  const float* c3b  = (const float*)d_in[6];
  const float* emb  = (const float*)d_in[7];
  const float* inw  = (const float*)d_in[8];
  const float* inb  = (const float*)d_in[9];
  const float* outw = (const float*)d_in[10];
  const float* outb = (const float*)d_in[11];
  const float* lng  = (const float*)d_in[12];
  const float* lnb  = (const float*)d_in[13];
  const float* l1w  = (const float*)d_in[14];
  const float* l1b  = (const float*)d_in[15];
  const float* l2w  = (const float*)d_in[16];
  const float* l2b  = (const float*)d_in[17];
  const float* posw = (const float*)d_in[18];
  const float* posb = (const float*)d_in[19];
  const float* numw = (const float*)d_in[20];
  const float* numb = (const float*)d_in[21];
  float* out = (float*)d_out;

  cudaFuncSetAttribute(k_conv3, cudaFuncAttributeMaxDynamicSharedMemorySize, 121 * 128 * 4);
  cudaFuncSetAttribute(k_attn,  cudaFuncAttributeMaxDynamicSharedMemorySize, 187920);

  /* partitionable (foldlike) split of key(42) = (0, 42):
     child key i = both outputs of threefry(key, (0, i)) */
  unsigned k1a, k1b, k2a, k2b;
  tf2x32(0u, 42u, 0u, 0u, &k1a, &k1b);
  tf2x32(0u, 42u, 0u, 1u, &k2a, &k2b);

  float *px, *pc, *pqkv; float4* pwv;
  cudaGetSymbolAddress((void**)&px,   g_x);
  cudaGetSymbolAddress((void**)&pc,   g_c);
  cudaGetSymbolAddress((void**)&pqkv, g_qkv);
  cudaGetSymbolAddress((void**)&pwv,  g_wv);

  k_digits<<<ROWS / 256, 256>>>(s);
  k_M<<<90, 128>>>(c1w, c1b, c2w);
  k_wtrans<<<240, 256>>>(c3w, inw, outw, l1w, l2w);
  k_conv3<<<BATCH, 256, 121 * 128 * 4>>>(c2b, c3b, emb);
  k_qkv<<<ROWS / 32, 256>>>(px, pwv, inb, pqkv);
  k_attn<<<BATCH, 384, 187920>>>(out + 2 * BATCH);
  k_out_ln<<<ROWS / 32, 256>>>(pc, pwv + 12288, outb, lng, lnb, px);
  k_mlp<<<ROWS / 32, 256>>>(px, pwv + 16384, l1b, pwv + 20480, l2b, pc);
  k_heads<<<BATCH, 128>>>(posw, posb, numw, numb, out, k1a, k1b, k2a, k2b);
}